// round 3
// baseline (speedup 1.0000x reference)
#include <cuda_runtime.h>
#include <mma.h>

using namespace nvcuda;

#define D_IN   4096
#define D_OUTD 4096
#define NEXP   8
#define RANKD  16
#define ERD    (NEXP * RANKD)   // 128
#define SCALINGF 2.0f
#define T_MAX  8192

// scratch: weighted LoRA hidden h[T, 128]
__device__ float g_h[T_MAX * ERD];

// ---------------------------------------------------------------------------
// Generic tiled WMMA TF32 GEMM:  C[M,N] (+)= A[M,K] * B^T
// LAYOUT 0: B element (k,n) = Bg[n*K + k]           (row-major [N,K])
// LAYOUT 1: B element (k,n) = Bg[(k>>4)*(D_OUTD*RANKD) + n*RANKD + (k&15)]
//           (expert layout [E, D_OUT, R], k = e*16 + r)
// Tiles: BM=128, BN=128, BK=32; 8 warps (2 x 4), warp tile 64x32.
// ---------------------------------------------------------------------------
#define BKT 32
#define LDT 40   // padded smem stride (floats); 40*4=160B, multiple of 32B

template <int LAYOUT, bool ACCUM>
__global__ __launch_bounds__(256)
void gemm_tf32_kernel(const float* __restrict__ Ag,
                      const float* __restrict__ Bg,
                      float* __restrict__ Cg,
                      int M, int N, int K)
{
    __shared__ float As[128 * LDT];
    __shared__ float Bs[128 * LDT];

    const int tid = threadIdx.x;
    const int warpId = tid >> 5;
    const int wm = warpId & 1;   // 0..1  (M dir)
    const int wn = warpId >> 1;  // 0..3  (N dir)

    const int m0 = blockIdx.y * 128;
    const int n0 = blockIdx.x * 128;

    wmma::fragment<wmma::accumulator, 16, 16, 8, float> acc[4][2];
#pragma unroll
    for (int i = 0; i < 4; i++)
#pragma unroll
        for (int j = 0; j < 2; j++)
            wmma::fill_fragment(acc[i][j], 0.0f);

    for (int k0 = 0; k0 < K; k0 += BKT) {
        // ---- load A tile [128 x 32] as float4 ----
#pragma unroll
        for (int it = 0; it < 4; it++) {
            int idx4 = tid + it * 256;       // 0..1023
            int row  = idx4 >> 3;            // 8 float4 per row
            int col4 = idx4 & 7;
            float4 v = *(const float4*)(Ag + (size_t)(m0 + row) * K + k0 + col4 * 4);
            *(float4*)(&As[row * LDT + col4 * 4]) = v;
        }
        // ---- load B tile: column n holds k=0..31 at Bs[n*LDT + k] ----
#pragma unroll
        for (int it = 0; it < 4; it++) {
            int idx4 = tid + it * 256;
            int n    = idx4 >> 3;
            int k4   = idx4 & 7;
            float4 v;
            if (LAYOUT == 0) {
                v = *(const float4*)(Bg + (size_t)(n0 + n) * K + k0 + k4 * 4);
            } else {
                int kbase = k0 + k4 * 4;
                int e = kbase >> 4;
                int r = kbase & 15;
                v = *(const float4*)(Bg + (size_t)e * (D_OUTD * RANKD)
                                        + (size_t)(n0 + n) * RANKD + r);
            }
            *(float4*)(&Bs[n * LDT + k4 * 4]) = v;
        }
        __syncthreads();

#pragma unroll
        for (int kk = 0; kk < BKT; kk += 8) {
            wmma::fragment<wmma::matrix_a, 16, 16, 8, wmma::precision::tf32, wmma::row_major> af[4];
            wmma::fragment<wmma::matrix_b, 16, 16, 8, wmma::precision::tf32, wmma::col_major> bf[2];
#pragma unroll
            for (int i = 0; i < 4; i++) {
                wmma::load_matrix_sync(af[i], &As[(wm * 64 + i * 16) * LDT + kk], LDT);
#pragma unroll
                for (int e = 0; e < af[i].num_elements; e++)
                    af[i].x[e] = wmma::__float_to_tf32(af[i].x[e]);
            }
#pragma unroll
            for (int j = 0; j < 2; j++) {
                wmma::load_matrix_sync(bf[j], &Bs[(wn * 32 + j * 16) * LDT + kk], LDT);
#pragma unroll
                for (int e = 0; e < bf[j].num_elements; e++)
                    bf[j].x[e] = wmma::__float_to_tf32(bf[j].x[e]);
            }
#pragma unroll
            for (int i = 0; i < 4; i++)
#pragma unroll
                for (int j = 0; j < 2; j++)
                    wmma::mma_sync(acc[i][j], af[i], bf[j], acc[i][j]);
        }
        __syncthreads();
    }

    // ---- epilogue ----
#pragma unroll
    for (int i = 0; i < 4; i++) {
#pragma unroll
        for (int j = 0; j < 2; j++) {
            float* cp = Cg + (size_t)(m0 + wm * 64 + i * 16) * N + n0 + wn * 32 + j * 16;
            if (ACCUM) {
                wmma::fragment<wmma::accumulator, 16, 16, 8, float> cf;
                wmma::load_matrix_sync(cf, cp, N, wmma::mem_row_major);
#pragma unroll
                for (int e = 0; e < cf.num_elements; e++)
                    acc[i][j].x[e] += cf.x[e];
            }
            wmma::store_matrix_sync(cp, acc[i][j], N, wmma::mem_row_major);
        }
    }
}

// ---------------------------------------------------------------------------
// Router: logits = x @ W_router^T, top-2, softmax, scale h in place
// one block per token, 256 threads
// ---------------------------------------------------------------------------
__global__ __launch_bounds__(256)
void router_kernel(const float* __restrict__ x,
                   const float* __restrict__ Wr,
                   float* __restrict__ h)
{
    const int t = blockIdx.x;
    const float* xr = x + (size_t)t * D_IN;

    float acc[NEXP];
#pragma unroll
    for (int e = 0; e < NEXP; e++) acc[e] = 0.0f;

    for (int j = threadIdx.x; j < D_IN; j += 256) {
        float xv = xr[j];
#pragma unroll
        for (int e = 0; e < NEXP; e++)
            acc[e] += xv * Wr[e * D_IN + j];
    }

    // warp reduce
#pragma unroll
    for (int off = 16; off > 0; off >>= 1)
#pragma unroll
        for (int e = 0; e < NEXP; e++)
            acc[e] += __shfl_xor_sync(0xffffffffu, acc[e], off);

    __shared__ float sred[8][NEXP];
    const int warp = threadIdx.x >> 5;
    const int lane = threadIdx.x & 31;
    if (lane == 0)
#pragma unroll
        for (int e = 0; e < NEXP; e++) sred[warp][e] = acc[e];
    __syncthreads();

    __shared__ float wv[NEXP];
    if (threadIdx.x == 0) {
        float l[NEXP];
#pragma unroll
        for (int e = 0; e < NEXP; e++) {
            float s = 0.0f;
#pragma unroll
            for (int w = 0; w < 8; w++) s += sred[w][e];
            l[e] = s;
        }
        // top-2 (first occurrence on ties, matching jax.lax.top_k)
        int i0 = 0;
#pragma unroll
        for (int e = 1; e < NEXP; e++) if (l[e] > l[i0]) i0 = e;
        int i1 = -1;
#pragma unroll
        for (int e = 0; e < NEXP; e++) {
            if (e == i0) continue;
            if (i1 < 0 || l[e] > l[i1]) i1 = e;
        }
        float m  = l[i0];
        float e0 = expf(l[i0] - m);
        float e1 = expf(l[i1] - m);
        float s  = e0 + e1;
#pragma unroll
        for (int e = 0; e < NEXP; e++) wv[e] = 0.0f;
        wv[i0] = e0 / s;
        wv[i1] = e1 / s;
    }
    __syncthreads();

    if (threadIdx.x < ERD) {
        int e = threadIdx.x >> 4;
        h[(size_t)t * ERD + threadIdx.x] *= wv[e] * SCALINGF;
    }
}

// ---------------------------------------------------------------------------
// out[t, o] = b_base[o]  (bias broadcast init; GEMMs then accumulate)
// ---------------------------------------------------------------------------
__global__ __launch_bounds__(256)
void init_bias_kernel(float* __restrict__ out, const float* __restrict__ b, int total4)
{
    int i4 = blockIdx.x * blockDim.x + threadIdx.x;
    if (i4 < total4) {
        int col = (i4 * 4) & (D_OUTD - 1);
        float4 bv = *(const float4*)(b + col);
        *(float4*)(out + (size_t)i4 * 4) = bv;
    }
}

// ---------------------------------------------------------------------------
extern "C" void kernel_launch(void* const* d_in, const int* in_sizes, int n_in,
                              void* d_out, int out_size)
{
    const float* x  = (const float*)d_in[0];   // [T, 4096]
    const float* Wb = (const float*)d_in[1];   // [4096, 4096]
    const float* bb = (const float*)d_in[2];   // [4096]
    const float* Wr = (const float*)d_in[3];   // [8, 4096]
    const float* Aw = (const float*)d_in[4];   // [8,16,4096] == [128,4096]
    const float* Bw = (const float*)d_in[5];   // [8,4096,16]
    float* out = (float*)d_out;

    const int T = in_sizes[0] / D_IN;          // 8192

    float* hptr = nullptr;
    cudaGetSymbolAddress((void**)&hptr, g_h);

    dim3 blk(256);

    // 1) h = x @ A_flat^T   [T,128]
    {
        dim3 grid(ERD / 128, T / 128);
        gemm_tf32_kernel<0, false><<<grid, blk>>>(x, Aw, hptr, T, ERD, D_IN);
    }
    // 2) router: top-2 softmax weights, scale h in place (incl. SCALING)
    router_kernel<<<T, blk>>>(x, Wr, hptr);

    // 3) out = bias broadcast
    {
        int total4 = (T * D_OUTD) / 4;
        init_bias_kernel<<<(total4 + 255) / 256, blk>>>(out, bb, total4);
    }
    // 4) out += x @ W_base^T
    {
        dim3 grid(D_OUTD / 128, T / 128);
        gemm_tf32_kernel<0, true><<<grid, blk>>>(x, Wb, out, T, D_OUTD, D_IN);
    }
    // 5) out += h_weighted @ B_flat   (expert layout)
    {
        dim3 grid(D_OUTD / 128, T / 128);
        gemm_tf32_kernel<1, true><<<grid, blk>>>(hptr, Bw, out, T, D_OUTD, ERD);
    }
}

// round 6
// speedup vs baseline: 1.4059x; 1.4059x over previous
#include <cuda_runtime.h>
#include <mma.h>
#include <cstdint>

using namespace nvcuda;

#define D_INc   4096
#define D_OUTc  4096
#define NEXP    8
#define RANKD   16
#define ERD     128          // NEXP * RANKD
#define SCALINGF 2.0f
#define T_MAXc  8192

// scratch: weighted LoRA hidden h'[T,128] and repacked B_flat[4096,128]
__device__ float g_h[T_MAXc * ERD];
__device__ float g_Bf[D_OUTc * ERD];

// ---------------------------------------------------------------------------
// cp.async helpers (sm_80 baseline — OK at compute_103)
// ---------------------------------------------------------------------------
__device__ __forceinline__ void cpa16(uint32_t dst, const void* src) {
    asm volatile("cp.async.cg.shared.global [%0], [%1], 16;" :: "r"(dst), "l"(src));
}
#define CP_COMMIT() asm volatile("cp.async.commit_group;")
#define CP_WAIT0()  asm volatile("cp.async.wait_group 0;")

// ---------------------------------------------------------------------------
// Fused tiled WMMA TF32 GEMM with cp.async 2-stage pipeline.
//   C[M, N] = concat-K GEMM + bias:
//     chunks 0..nc1-1       : A = pA1 (ldA1), B = pB1 (ldB1), K offset c*32
//     chunks nc1..nc1+nc2-1 : A = pA2 (ldA2), B = pB2 (ldB2)
//   Block tile 128x128, BK=32 floats, 256 threads (8 warps, warp 64x32).
//   Epilogue: accum -> smem -> +bias -> coalesced float4 stores (no RMW).
// ---------------------------------------------------------------------------
#define LDT     36            // smem row stride (floats) in mainloop tiles
#define STAGE_F (128 * LDT)   // 4608 floats per matrix tile
#define STAGE_B (2 * STAGE_F * 4)  // 36864 bytes per stage (A + B)
#define LDE     132           // epilogue smem stride (floats)

__global__ __launch_bounds__(256, 2)
void fused_gemm(const float* __restrict__ pA1, int ldA1,
                const float* __restrict__ pB1, int ldB1,
                const float* __restrict__ pA2, int ldA2,
                const float* __restrict__ pB2, int ldB2,
                int nc1, int nc2,
                const float* __restrict__ bias,
                float* __restrict__ out, int ldC)
{
    extern __shared__ __align__(16) char smem[];
    float* sb = (float*)smem;                      // bias tile [128]
    char*  stage_base = smem + 1024;
    const uint32_t stage_s = (uint32_t)__cvta_generic_to_shared(stage_base);

    const int tid  = threadIdx.x;
    const int warpId = tid >> 5;
    const int wm = warpId & 1;    // 0..1 (M dir)
    const int wn = warpId >> 1;   // 0..3 (N dir)
    const int m0 = blockIdx.y * 128;
    const int n0 = blockIdx.x * 128;
    const int NC = nc1 + nc2;

    // bias tile (zeros when absent)
    for (int i = tid; i < 128; i += 256)
        sb[i] = bias ? bias[n0 + i] : 0.0f;

    wmma::fragment<wmma::accumulator, 16, 16, 8, float> acc[4][2];
#pragma unroll
    for (int i = 0; i < 4; i++)
#pragma unroll
        for (int j = 0; j < 2; j++)
            wmma::fill_fragment(acc[i][j], 0.0f);

    // ---- async load of one K-chunk into stage st ----
    auto load_chunk = [&](int c, int st) {
        const float* bA; int lda; const float* bB; int ldb; int kof;
        if (c < nc1) { bA = pA1; lda = ldA1; bB = pB1; ldb = ldB1; kof = c * 32; }
        else         { bA = pA2; lda = ldA2; bB = pB2; ldb = ldB2; kof = (c - nc1) * 32; }
        uint32_t sA = stage_s + st * STAGE_B;
        uint32_t sB = sA + STAGE_F * 4;
#pragma unroll
        for (int it = 0; it < 4; it++) {
            int idx4 = tid + it * 256;   // 0..1023
            int row  = idx4 >> 3;        // 8 x 16B segs per row
            int c4   = idx4 & 7;
            cpa16(sA + (uint32_t)(row * LDT + c4 * 4) * 4,
                  bA + (size_t)(m0 + row) * lda + kof + c4 * 4);
            cpa16(sB + (uint32_t)(row * LDT + c4 * 4) * 4,
                  bB + (size_t)(n0 + row) * ldb + kof + c4 * 4);
        }
        CP_COMMIT();
    };

    // prologue
    load_chunk(0, 0);

    for (int c = 0; c < NC; c++) {
        CP_WAIT0();
        __syncthreads();                 // chunk c visible to all threads
        if (c + 1 < NC) load_chunk(c + 1, (c + 1) & 1);

        const float* As = (const float*)(stage_base + (c & 1) * STAGE_B);
        const float* Bs = As + STAGE_F;

#pragma unroll
        for (int kk = 0; kk < 32; kk += 8) {
            wmma::fragment<wmma::matrix_a, 16, 16, 8, wmma::precision::tf32, wmma::row_major> af[4];
            wmma::fragment<wmma::matrix_b, 16, 16, 8, wmma::precision::tf32, wmma::col_major> bf[2];
#pragma unroll
            for (int i = 0; i < 4; i++) {
                wmma::load_matrix_sync(af[i], &As[(wm * 64 + i * 16) * LDT + kk], LDT);
#pragma unroll
                for (int e = 0; e < af[i].num_elements; e++)
                    af[i].x[e] = wmma::__float_to_tf32(af[i].x[e]);
            }
#pragma unroll
            for (int j = 0; j < 2; j++) {
                wmma::load_matrix_sync(bf[j], &Bs[(wn * 32 + j * 16) * LDT + kk], LDT);
#pragma unroll
                for (int e = 0; e < bf[j].num_elements; e++)
                    bf[j].x[e] = wmma::__float_to_tf32(bf[j].x[e]);
            }
#pragma unroll
            for (int i = 0; i < 4; i++)
#pragma unroll
                for (int j = 0; j < 2; j++)
                    wmma::mma_sync(acc[i][j], af[i], bf[j], acc[i][j]);
        }
        __syncthreads();                 // compute done before stage reuse
    }

    // ---- epilogue: frags -> smem -> +bias -> coalesced stores ----
    float* sE = (float*)stage_base;      // 128 x LDE floats = 67.6KB (fits stages)
#pragma unroll
    for (int i = 0; i < 4; i++)
#pragma unroll
        for (int j = 0; j < 2; j++)
            wmma::store_matrix_sync(&sE[(wm * 64 + i * 16) * LDE + wn * 32 + j * 16],
                                    acc[i][j], LDE, wmma::mem_row_major);
    __syncthreads();

#pragma unroll
    for (int it = 0; it < 16; it++) {
        int i4  = tid + it * 256;        // 0..4095 float4s
        int row = i4 >> 5;
        int c4  = i4 & 31;
        float4 v = *(const float4*)&sE[row * LDE + c4 * 4];
        v.x += sb[c4 * 4 + 0];
        v.y += sb[c4 * 4 + 1];
        v.z += sb[c4 * 4 + 2];
        v.w += sb[c4 * 4 + 3];
        *(float4*)(out + (size_t)(m0 + row) * ldC + n0 + c4 * 4) = v;
    }
}

// ---------------------------------------------------------------------------
// Router: logits = x @ Wr^T, top-2 softmax, scale h' in place (incl SCALING)
// ---------------------------------------------------------------------------
__global__ __launch_bounds__(256)
void router_kernel(const float* __restrict__ x,
                   const float* __restrict__ Wr,
                   float* __restrict__ h)
{
    const int t = blockIdx.x;
    const float* xr = x + (size_t)t * D_INc;

    float acc[NEXP];
#pragma unroll
    for (int e = 0; e < NEXP; e++) acc[e] = 0.0f;
    for (int j = threadIdx.x; j < D_INc; j += 256) {
        float xv = xr[j];
#pragma unroll
        for (int e = 0; e < NEXP; e++) acc[e] += xv * Wr[e * D_INc + j];
    }
#pragma unroll
    for (int off = 16; off > 0; off >>= 1)
#pragma unroll
        for (int e = 0; e < NEXP; e++) acc[e] += __shfl_xor_sync(0xffffffffu, acc[e], off);

    __shared__ float sred[8][NEXP];
    const int warp = threadIdx.x >> 5;
    const int lane = threadIdx.x & 31;
    if (lane == 0)
#pragma unroll
        for (int e = 0; e < NEXP; e++) sred[warp][e] = acc[e];
    __syncthreads();

    __shared__ float wv[NEXP];
    if (threadIdx.x == 0) {
        float l[NEXP];
#pragma unroll
        for (int e = 0; e < NEXP; e++) {
            float s = 0.0f;
#pragma unroll
            for (int w = 0; w < 8; w++) s += sred[w][e];
            l[e] = s;
        }
        int i0 = 0;
#pragma unroll
        for (int e = 1; e < NEXP; e++) if (l[e] > l[i0]) i0 = e;
        int i1 = -1;
#pragma unroll
        for (int e = 0; e < NEXP; e++) {
            if (e == i0) continue;
            if (i1 < 0 || l[e] > l[i1]) i1 = e;
        }
        float m  = l[i0];
        float e0 = expf(l[i0] - m);
        float e1 = expf(l[i1] - m);
        float s  = e0 + e1;
#pragma unroll
        for (int e = 0; e < NEXP; e++) wv[e] = 0.0f;
        wv[i0] = e0 / s;
        wv[i1] = e1 / s;
    }
    __syncthreads();

    if (threadIdx.x < ERD) {
        int e = threadIdx.x >> 4;
        h[(size_t)t * ERD + threadIdx.x] *= wv[e] * SCALINGF;
    }
}

// ---------------------------------------------------------------------------
// Repack B: Bf[n, e*16+r] = Bw[e, n, r]   (-> row-major [4096, 128] K-major)
// ---------------------------------------------------------------------------
__global__ __launch_bounds__(256)
void repack_B_kernel(const float* __restrict__ Bw, float* __restrict__ Bf)
{
    int idx = blockIdx.x * 256 + threadIdx.x;   // over 4096 * 32 float4s
    int n  = idx >> 5;
    int j4 = idx & 31;
    int j  = j4 * 4;
    int e  = j >> 4;
    int r  = j & 15;
    float4 v = *(const float4*)(Bw + (size_t)e * (D_OUTc * RANKD) + (size_t)n * RANKD + r);
    *(float4*)(Bf + (size_t)n * ERD + j) = v;
}

// ---------------------------------------------------------------------------
extern "C" void kernel_launch(void* const* d_in, const int* in_sizes, int n_in,
                              void* d_out, int out_size)
{
    const float* x  = (const float*)d_in[0];   // [T, 4096]
    const float* Wb = (const float*)d_in[1];   // [4096, 4096]
    const float* bb = (const float*)d_in[2];   // [4096]
    const float* Wr = (const float*)d_in[3];   // [8, 4096]
    const float* Aw = (const float*)d_in[4];   // [8,16,4096] == [128,4096]
    const float* Bw = (const float*)d_in[5];   // [8,4096,16]
    float* out = (float*)d_out;

    const int T = in_sizes[0] / D_INc;         // 8192

    float *hptr = nullptr, *bfptr = nullptr;
    cudaGetSymbolAddress((void**)&hptr,  g_h);
    cudaGetSymbolAddress((void**)&bfptr, g_Bf);

    constexpr int SMEM = 1024 + 2 * STAGE_B;   // 74752 bytes

    static bool attr_done = false;
    if (!attr_done) {
        cudaFuncSetAttribute(fused_gemm, cudaFuncAttributeMaxDynamicSharedMemorySize, SMEM);
        attr_done = true;
    }

    // 1) repack expert B into K-major [4096, 128]
    repack_B_kernel<<<(D_OUTc * 32) / 256, 256>>>(Bw, bfptr);

    // 2) h = x @ A_flat^T   [T, 128]   (no bias)
    fused_gemm<<<dim3(1, T / 128), 256, SMEM>>>(
        x, D_INc, Aw, D_INc,
        x, D_INc, Aw, D_INc,
        D_INc / 32, 0, nullptr, hptr, ERD);

    // 3) router: scale h by top-2 softmax weights * SCALING
    router_kernel<<<T, 256>>>(x, Wr, hptr);

    // 4) out = [x | h'] @ [Wb | Bf]^T + bias   (base + lora fused, no RMW)
    fused_gemm<<<dim3(D_OUTc / 128, T / 128), 256, SMEM>>>(
        x, D_INc, Wb, D_INc,
        hptr, ERD, bfptr, ERD,
        D_INc / 32, ERD / 32, bb, out, D_OUTc);
}

// round 7
// speedup vs baseline: 1.5026x; 1.0688x over previous
#include <cuda_runtime.h>
#include <mma.h>
#include <cstdint>

using namespace nvcuda;

#define D_INc   4096
#define D_OUTc  4096
#define NEXP    8
#define RANKD   16
#define ERD     128          // NEXP * RANKD
#define SCALINGF 2.0f
#define T_MAXc  8192
#define KSPLIT  4

// scratch (tf32-pre-rounded copies + partials)
__device__ float g_xr [T_MAXc * D_INc];          // 128MB rounded x
__device__ float g_Wbr[D_OUTc * D_INc];          // 64MB  rounded W_base
__device__ float g_Ar [ERD * D_INc];             // 2MB   rounded A_flat
__device__ float g_Bf [D_OUTc * ERD];            // 2MB   repacked+rounded B_flat
__device__ float g_hp [KSPLIT * T_MAXc * ERD];   // 16MB  h partials (split-K)
__device__ float g_h  [T_MAXc * ERD];            // 4MB   weighted+rounded h'

// ---------------------------------------------------------------------------
// cp.async helpers (sm_80 baseline — OK at compute_103)
// ---------------------------------------------------------------------------
__device__ __forceinline__ void cpa16(uint32_t dst, const void* src) {
    asm volatile("cp.async.cg.shared.global [%0], [%1], 16;" :: "r"(dst), "l"(src));
}
#define CP_COMMIT() asm volatile("cp.async.commit_group;")
#define CP_WAIT1()  asm volatile("cp.async.wait_group 1;")

// ---------------------------------------------------------------------------
// Fused tiled WMMA TF32 GEMM, 3-stage cp.async pipeline, NO in-loop converts
// (operands pre-rounded to tf32 in gmem).
//   chunks 0..nc1-1       : A = pA1 (ldA1), B = pB1 (ldB1), K off kbase+c*32
//   chunks nc1..nc1+nc2-1 : A = pA2 (ldA2), B = pB2 (ldB2)
//   ksplit != 0: blockIdx.x = K-slice (n0 = 0, out += slice*sliceStride,
//                kbase = slice*nc1*32)
//   Block tile 128x128, BK=32, 256 threads (8 warps, warp 64x32).
// ---------------------------------------------------------------------------
#define LDT     36                  // smem row stride (floats)
#define STAGE_F (128 * LDT)         // floats per matrix tile
#define STAGE_B (2 * STAGE_F * 4)   // 36864 B per stage (A + B)
#define NSTG    3
#define LDE     132                 // epilogue smem stride (floats)

__global__ __launch_bounds__(256, 2)
void fused_gemm(const float* __restrict__ pA1, int ldA1,
                const float* __restrict__ pB1, int ldB1,
                const float* __restrict__ pA2, int ldA2,
                const float* __restrict__ pB2, int ldB2,
                int nc1, int nc2,
                const float* __restrict__ bias,
                float* __restrict__ out, int ldC,
                int ksplit, int sliceStride)
{
    extern __shared__ __align__(16) char smem[];
    float* sb = (float*)smem;                      // bias tile [128]
    char*  stage_base = smem + 1024;
    const uint32_t stage_s = (uint32_t)__cvta_generic_to_shared(stage_base);

    const int tid  = threadIdx.x;
    const int warpId = tid >> 5;
    const int wm = warpId & 1;    // 0..1 (M dir)
    const int wn = warpId >> 1;   // 0..3 (N dir)
    const int m0 = blockIdx.y * 128;
    const int NC = nc1 + nc2;

    int n0, kbase;
    float* outp = out;
    if (ksplit) {
        n0 = 0;
        kbase = blockIdx.x * nc1 * 32;
        outp  = out + (size_t)blockIdx.x * sliceStride;
    } else {
        n0 = blockIdx.x * 128;
        kbase = 0;
    }

    for (int i = tid; i < 128; i += 256)
        sb[i] = bias ? bias[n0 + i] : 0.0f;

    wmma::fragment<wmma::accumulator, 16, 16, 8, float> acc[4][2];
#pragma unroll
    for (int i = 0; i < 4; i++)
#pragma unroll
        for (int j = 0; j < 2; j++)
            wmma::fill_fragment(acc[i][j], 0.0f);

    auto load_chunk = [&](int c, int st) {
        const float* bA; int lda; const float* bB; int ldb; int kof;
        if (c < nc1) { bA = pA1; lda = ldA1; bB = pB1; ldb = ldB1; kof = kbase + c * 32; }
        else         { bA = pA2; lda = ldA2; bB = pB2; ldb = ldB2; kof = (c - nc1) * 32; }
        uint32_t sA = stage_s + st * STAGE_B;
        uint32_t sB = sA + STAGE_F * 4;
#pragma unroll
        for (int it = 0; it < 4; it++) {
            int idx4 = tid + it * 256;   // 0..1023
            int row  = idx4 >> 3;
            int c4   = idx4 & 7;
            cpa16(sA + (uint32_t)(row * LDT + c4 * 4) * 4,
                  bA + (size_t)(m0 + row) * lda + kof + c4 * 4);
            cpa16(sB + (uint32_t)(row * LDT + c4 * 4) * 4,
                  bB + (size_t)(n0 + row) * ldb + kof + c4 * 4);
        }
        CP_COMMIT();
    };

    // prologue: 2 chunks in flight
    load_chunk(0, 0);
    load_chunk(1, 1);

    int st_c = 0;   // compute stage
    int st_l = 2;   // next load stage
    for (int c = 0; c < NC; c++) {
        CP_WAIT1();                   // chunk c landed (<=1 group pending)
        __syncthreads();              // everyone done with stage st_l's old data
        if (c + 2 < NC) {
            load_chunk(c + 2, st_l);
            if (++st_l == NSTG) st_l = 0;
        }

        const float* As = (const float*)(stage_base + st_c * STAGE_B);
        const float* Bs = As + STAGE_F;
        if (++st_c == NSTG) st_c = 0;

#pragma unroll
        for (int kk = 0; kk < 32; kk += 8) {
            wmma::fragment<wmma::matrix_a, 16, 16, 8, wmma::precision::tf32, wmma::row_major> af[4];
            wmma::fragment<wmma::matrix_b, 16, 16, 8, wmma::precision::tf32, wmma::col_major> bf[2];
#pragma unroll
            for (int i = 0; i < 4; i++)
                wmma::load_matrix_sync(af[i], &As[(wm * 64 + i * 16) * LDT + kk], LDT);
#pragma unroll
            for (int j = 0; j < 2; j++)
                wmma::load_matrix_sync(bf[j], &Bs[(wn * 32 + j * 16) * LDT + kk], LDT);
            // NOTE: no cvt — operands pre-rounded to tf32 in gmem
#pragma unroll
            for (int i = 0; i < 4; i++)
#pragma unroll
                for (int j = 0; j < 2; j++)
                    wmma::mma_sync(acc[i][j], af[i], bf[j], acc[i][j]);
        }
    }

    // ---- epilogue: frags -> smem -> +bias -> coalesced float4 stores ----
    __syncthreads();
    float* sE = (float*)stage_base;   // 128 x LDE floats = 67.6KB, fits stages
#pragma unroll
    for (int i = 0; i < 4; i++)
#pragma unroll
        for (int j = 0; j < 2; j++)
            wmma::store_matrix_sync(&sE[(wm * 64 + i * 16) * LDE + wn * 32 + j * 16],
                                    acc[i][j], LDE, wmma::mem_row_major);
    __syncthreads();

#pragma unroll
    for (int it = 0; it < 16; it++) {
        int i4  = tid + it * 256;
        int row = i4 >> 5;
        int c4  = i4 & 31;
        float4 v = *(const float4*)&sE[row * LDE + c4 * 4];
        v.x += sb[c4 * 4 + 0];
        v.y += sb[c4 * 4 + 1];
        v.z += sb[c4 * 4 + 2];
        v.w += sb[c4 * 4 + 3];
        *(float4*)(outp + (size_t)(m0 + row) * ldC + n0 + c4 * 4) = v;
    }
}

// ---------------------------------------------------------------------------
// round-to-tf32 elementwise copy (float4 granularity)
// ---------------------------------------------------------------------------
__global__ __launch_bounds__(256)
void round_copy_kernel(const float* __restrict__ src, float* __restrict__ dst, int n4)
{
    int i = blockIdx.x * 256 + threadIdx.x;
    if (i < n4) {
        float4 v = *(const float4*)(src + (size_t)i * 4);
        v.x = wmma::__float_to_tf32(v.x);
        v.y = wmma::__float_to_tf32(v.y);
        v.z = wmma::__float_to_tf32(v.z);
        v.w = wmma::__float_to_tf32(v.w);
        *(float4*)(dst + (size_t)i * 4) = v;
    }
}

// ---------------------------------------------------------------------------
// Repack + round B: Bf[n, e*16+r] = tf32(Bw[e, n, r])
// ---------------------------------------------------------------------------
__global__ __launch_bounds__(256)
void repack_B_kernel(const float* __restrict__ Bw, float* __restrict__ Bf)
{
    int idx = blockIdx.x * 256 + threadIdx.x;   // over 4096 * 32 float4s
    int n  = idx >> 5;
    int j4 = idx & 31;
    int j  = j4 * 4;
    int e  = j >> 4;
    int r  = j & 15;
    float4 v = *(const float4*)(Bw + (size_t)e * (D_OUTc * RANKD) + (size_t)n * RANKD + r);
    v.x = wmma::__float_to_tf32(v.x);
    v.y = wmma::__float_to_tf32(v.y);
    v.z = wmma::__float_to_tf32(v.z);
    v.w = wmma::__float_to_tf32(v.w);
    *(float4*)(Bf + (size_t)n * ERD + j) = v;
}

// ---------------------------------------------------------------------------
// Router: logits = x @ Wr^T, top-2 softmax; h' = round(sum_s hp[s] * wv * SCALING)
// ---------------------------------------------------------------------------
__global__ __launch_bounds__(256)
void router_kernel(const float* __restrict__ x,
                   const float* __restrict__ Wr,
                   const float* __restrict__ hp,   // [KSPLIT][T][128]
                   float* __restrict__ h,
                   int T)
{
    const int t = blockIdx.x;
    const float* xr = x + (size_t)t * D_INc;

    float acc[NEXP];
#pragma unroll
    for (int e = 0; e < NEXP; e++) acc[e] = 0.0f;
    for (int j = threadIdx.x; j < D_INc; j += 256) {
        float xv = xr[j];
#pragma unroll
        for (int e = 0; e < NEXP; e++) acc[e] += xv * Wr[e * D_INc + j];
    }
#pragma unroll
    for (int off = 16; off > 0; off >>= 1)
#pragma unroll
        for (int e = 0; e < NEXP; e++) acc[e] += __shfl_xor_sync(0xffffffffu, acc[e], off);

    __shared__ float sred[8][NEXP];
    const int warp = threadIdx.x >> 5;
    const int lane = threadIdx.x & 31;
    if (lane == 0)
#pragma unroll
        for (int e = 0; e < NEXP; e++) sred[warp][e] = acc[e];
    __syncthreads();

    __shared__ float wv[NEXP];
    if (threadIdx.x == 0) {
        float l[NEXP];
#pragma unroll
        for (int e = 0; e < NEXP; e++) {
            float s = 0.0f;
#pragma unroll
            for (int w = 0; w < 8; w++) s += sred[w][e];
            l[e] = s;
        }
        int i0 = 0;
#pragma unroll
        for (int e = 1; e < NEXP; e++) if (l[e] > l[i0]) i0 = e;
        int i1 = -1;
#pragma unroll
        for (int e = 0; e < NEXP; e++) {
            if (e == i0) continue;
            if (i1 < 0 || l[e] > l[i1]) i1 = e;
        }
        float m  = l[i0];
        float e0 = expf(l[i0] - m);
        float e1 = expf(l[i1] - m);
        float s  = e0 + e1;
#pragma unroll
        for (int e = 0; e < NEXP; e++) wv[e] = 0.0f;
        wv[i0] = e0 / s;
        wv[i1] = e1 / s;
    }
    __syncthreads();

    if (threadIdx.x < ERD) {
        int e = threadIdx.x >> 4;
        size_t base = (size_t)t * ERD + threadIdx.x;
        size_t ss = (size_t)T * ERD;
        float v = hp[base] + hp[base + ss] + hp[base + 2 * ss] + hp[base + 3 * ss];
        h[base] = wmma::__float_to_tf32(v * (wv[e] * SCALINGF));
    }
}

// ---------------------------------------------------------------------------
extern "C" void kernel_launch(void* const* d_in, const int* in_sizes, int n_in,
                              void* d_out, int out_size)
{
    const float* x  = (const float*)d_in[0];   // [T, 4096]
    const float* Wb = (const float*)d_in[1];   // [4096, 4096]
    const float* bb = (const float*)d_in[2];   // [4096]
    const float* Wr = (const float*)d_in[3];   // [8, 4096]
    const float* Aw = (const float*)d_in[4];   // [8,16,4096] == [128,4096]
    const float* Bw = (const float*)d_in[5];   // [8,4096,16]
    float* out = (float*)d_out;

    const int T = in_sizes[0] / D_INc;         // 8192

    float *xr, *wbr, *ar, *bf, *hp, *h;
    cudaGetSymbolAddress((void**)&xr,  g_xr);
    cudaGetSymbolAddress((void**)&wbr, g_Wbr);
    cudaGetSymbolAddress((void**)&ar,  g_Ar);
    cudaGetSymbolAddress((void**)&bf,  g_Bf);
    cudaGetSymbolAddress((void**)&hp,  g_hp);
    cudaGetSymbolAddress((void**)&h,   g_h);

    constexpr int SMEM = 1024 + NSTG * STAGE_B;   // 111,616 B

    static bool attr_done = false;
    if (!attr_done) {
        cudaFuncSetAttribute(fused_gemm, cudaFuncAttributeMaxDynamicSharedMemorySize, SMEM);
        attr_done = true;
    }

    // --- prepass: tf32-round all tensor operands ---
    {
        int n4x = T * D_INc / 4;
        round_copy_kernel<<<(n4x + 255) / 256, 256>>>(x, xr, n4x);
        int n4w = D_OUTc * D_INc / 4;
        round_copy_kernel<<<(n4w + 255) / 256, 256>>>(Wb, wbr, n4w);
        int n4a = ERD * D_INc / 4;
        round_copy_kernel<<<(n4a + 255) / 256, 256>>>(Aw, ar, n4a);
        repack_B_kernel<<<(D_OUTc * 32) / 256, 256>>>(Bw, bf);
    }

    // --- h partials = x @ A^T, split-K across 4 slices (grid 4 x 64) ---
    fused_gemm<<<dim3(KSPLIT, T / 128), 256, SMEM>>>(
        xr, D_INc, ar, D_INc,
        xr, D_INc, ar, D_INc,
        D_INc / 32 / KSPLIT, 0, nullptr, hp, ERD,
        1, T * ERD);

    // --- router: top-2 softmax weights, reduce partials, scale+round h' ---
    router_kernel<<<T, 256>>>(x, Wr, hp, h, T);

    // --- out = [x | h'] @ [Wb | Bf]^T + bias ---
    fused_gemm<<<dim3(D_OUTc / 128, T / 128), 256, SMEM>>>(
        xr, D_INc, wbr, D_INc,
        h, ERD, bf, ERD,
        D_INc / 32, ERD / 32, bb, out, D_OUTc,
        0, 0);
}

// round 10
// speedup vs baseline: 6.1300x; 4.0796x over previous
#include <cuda_runtime.h>
#include <cuda_fp16.h>
#include <mma.h>
#include <cstdint>

using namespace nvcuda;

#define D_INc   4096
#define D_OUTc  4096
#define NEXP    8
#define RANKD   16
#define ERD     128          // NEXP * RANKD
#define SCALINGF 2.0f
#define T_MAXc  8192
#define KSPLIT  4

// scratch: fp16 operand copies + fp32 split-K partials
__device__ __half g_xh [T_MAXc * D_INc];          // 64MB
__device__ __half g_Wbh[D_OUTc * D_INc];          // 32MB
__device__ __half g_Ah [ERD * D_INc];             // 1MB
__device__ __half g_Bfh[D_OUTc * ERD];            // 1MB  repacked B_flat
__device__ __half g_hh [T_MAXc * ERD];            // 2MB  weighted h'
__device__ float  g_hp [KSPLIT * T_MAXc * ERD];   // 16MB h partials

// ---------------------------------------------------------------------------
// cp.async helpers
// ---------------------------------------------------------------------------
__device__ __forceinline__ void cpa16(uint32_t dst, const void* src) {
    asm volatile("cp.async.cg.shared.global [%0], [%1], 16;" :: "r"(dst), "l"(src));
}
#define CP_COMMIT() asm volatile("cp.async.commit_group;")
#define CP_WAIT1()  asm volatile("cp.async.wait_group 1;")

// ---------------------------------------------------------------------------
// Fused tiled WMMA FP16 GEMM (fp32 accum), 3-stage cp.async pipeline.
//   C[M,N](fp32) = concat-K GEMM + bias, operands fp16:
//     chunks 0..nc1-1       : A = pA1 (ldA1), B = pB1 (ldB1), K off kbase+c*64
//     chunks nc1..nc1+nc2-1 : A = pA2 (ldA2), B = pB2 (ldB2)
//   ksplit != 0: blockIdx.x = K-slice (n0=0, out += slice*sliceStride,
//                kbase = slice*nc1*64)
//   Block tile 128x128, BK=64 halves, 256 threads (8 warps, warp 64x32).
// ---------------------------------------------------------------------------
#define BKH     64                    // halves per K chunk
#define LDTH    72                    // smem row stride (halves), +8 pad
#define TILE_H  (128 * LDTH)          // halves per matrix tile
#define STAGE_B (2 * TILE_H * 2)      // 36864 B per stage (A + B)
#define NSTG    3
#define LDE     132                   // epilogue smem stride (floats)

__global__ __launch_bounds__(256, 2)
void fused_gemm(const __half* __restrict__ pA1, int ldA1,
                const __half* __restrict__ pB1, int ldB1,
                const __half* __restrict__ pA2, int ldA2,
                const __half* __restrict__ pB2, int ldB2,
                int nc1, int nc2,
                const float* __restrict__ bias,
                float* __restrict__ out, int ldC,
                int ksplit, int sliceStride)
{
    extern __shared__ __align__(16) char smem[];
    float* sb = (float*)smem;                      // bias tile [128]
    char*  stage_base = smem + 1024;
    const uint32_t stage_s = (uint32_t)__cvta_generic_to_shared(stage_base);

    const int tid  = threadIdx.x;
    const int warpId = tid >> 5;
    const int wm = warpId & 1;    // 0..1 (M dir, 64 rows)
    const int wn = warpId >> 1;   // 0..3 (N dir, 32 cols)
    const int m0 = blockIdx.y * 128;
    const int NC = nc1 + nc2;

    int n0, kbase;
    float* outp = out;
    if (ksplit) {
        n0 = 0;
        kbase = blockIdx.x * nc1 * BKH;
        outp  = out + (size_t)blockIdx.x * sliceStride;
    } else {
        n0 = blockIdx.x * 128;
        kbase = 0;
    }

    for (int i = tid; i < 128; i += 256)
        sb[i] = bias ? bias[n0 + i] : 0.0f;

    wmma::fragment<wmma::accumulator, 16, 16, 16, float> acc[4][2];
#pragma unroll
    for (int i = 0; i < 4; i++)
#pragma unroll
        for (int j = 0; j < 2; j++)
            wmma::fill_fragment(acc[i][j], 0.0f);

    // ---- async load of one K-chunk (A[128x64h] + B[128x64h]) into stage st ----
    auto load_chunk = [&](int c, int st) {
        const __half* bA; int lda; const __half* bB; int ldb; int kof;
        if (c < nc1) { bA = pA1; lda = ldA1; bB = pB1; ldb = ldB1; kof = kbase + c * BKH; }
        else         { bA = pA2; lda = ldA2; bB = pB2; ldb = ldB2; kof = (c - nc1) * BKH; }
        uint32_t sA = stage_s + st * STAGE_B;
        uint32_t sB = sA + TILE_H * 2;
#pragma unroll
        for (int it = 0; it < 4; it++) {
            int idx = tid + it * 256;    // 0..1023 : 128 rows x 8 segs(16B)
            int row = idx >> 3;
            int sg  = idx & 7;
            cpa16(sA + (uint32_t)(row * LDTH + sg * 8) * 2,
                  bA + (size_t)(m0 + row) * lda + kof + sg * 8);
            cpa16(sB + (uint32_t)(row * LDTH + sg * 8) * 2,
                  bB + (size_t)(n0 + row) * ldb + kof + sg * 8);
        }
        CP_COMMIT();
    };

    // prologue: 2 chunks in flight
    load_chunk(0, 0);
    load_chunk(1, 1);

    int st_c = 0, st_l = 2;
    for (int c = 0; c < NC; c++) {
        CP_WAIT1();
        __syncthreads();
        if (c + 2 < NC) {
            load_chunk(c + 2, st_l);
            if (++st_l == NSTG) st_l = 0;
        }

        const __half* As = (const __half*)(stage_base + st_c * STAGE_B);
        const __half* Bs = As + TILE_H;
        if (++st_c == NSTG) st_c = 0;

#pragma unroll
        for (int kk = 0; kk < BKH; kk += 16) {
            wmma::fragment<wmma::matrix_a, 16, 16, 16, __half, wmma::row_major> af[4];
            wmma::fragment<wmma::matrix_b, 16, 16, 16, __half, wmma::col_major> bf[2];
#pragma unroll
            for (int i = 0; i < 4; i++)
                wmma::load_matrix_sync(af[i], &As[(wm * 64 + i * 16) * LDTH + kk], LDTH);
#pragma unroll
            for (int j = 0; j < 2; j++)
                wmma::load_matrix_sync(bf[j], &Bs[(wn * 32 + j * 16) * LDTH + kk], LDTH);
#pragma unroll
            for (int i = 0; i < 4; i++)
#pragma unroll
                for (int j = 0; j < 2; j++)
                    wmma::mma_sync(acc[i][j], af[i], bf[j], acc[i][j]);
        }
    }

    // ---- epilogue: frags -> smem(fp32) -> +bias -> coalesced float4 stores ----
    __syncthreads();
    float* sE = (float*)stage_base;    // 128 x LDE floats = 67.6KB, fits stages
#pragma unroll
    for (int i = 0; i < 4; i++)
#pragma unroll
        for (int j = 0; j < 2; j++)
            wmma::store_matrix_sync(&sE[(wm * 64 + i * 16) * LDE + wn * 32 + j * 16],
                                    acc[i][j], LDE, wmma::mem_row_major);
    __syncthreads();

#pragma unroll
    for (int it = 0; it < 16; it++) {
        int i4  = tid + it * 256;
        int row = i4 >> 5;
        int c4  = i4 & 31;
        float4 v = *(const float4*)&sE[row * LDE + c4 * 4];
        v.x += sb[c4 * 4 + 0];
        v.y += sb[c4 * 4 + 1];
        v.z += sb[c4 * 4 + 2];
        v.w += sb[c4 * 4 + 3];
        *(float4*)(outp + (size_t)(m0 + row) * ldC + n0 + c4 * 4) = v;
    }
}

// ---------------------------------------------------------------------------
// fp32 -> fp16 convert copy: 8 elems/thread
// ---------------------------------------------------------------------------
__global__ __launch_bounds__(256)
void to_half_kernel(const float* __restrict__ src, __half* __restrict__ dst, int n8)
{
    int i = blockIdx.x * 256 + threadIdx.x;
    if (i < n8) {
        const float4* s = (const float4*)(src + (size_t)i * 8);
        float4 a = s[0], b = s[1];
        __half2 h[4];
        h[0] = __floats2half2_rn(a.x, a.y);
        h[1] = __floats2half2_rn(a.z, a.w);
        h[2] = __floats2half2_rn(b.x, b.y);
        h[3] = __floats2half2_rn(b.z, b.w);
        *(uint4*)(dst + (size_t)i * 8) = *(uint4*)h;
    }
}

// ---------------------------------------------------------------------------
// Repack + convert B: Bfh[n][e*16+r] = fp16(Bw[e][n][r])
// ---------------------------------------------------------------------------
__global__ __launch_bounds__(256)
void repack_B_kernel(const float* __restrict__ Bw, __half* __restrict__ Bfh)
{
    int idx = blockIdx.x * 256 + threadIdx.x;   // over 4096 * 32 groups of 4
    int n  = idx >> 5;
    int j4 = idx & 31;
    int j  = j4 * 4;
    int e  = j >> 4;
    int r  = j & 15;
    float4 v = *(const float4*)(Bw + (size_t)e * (D_OUTc * RANKD) + (size_t)n * RANKD + r);
    __half2 h[2];
    h[0] = __floats2half2_rn(v.x, v.y);
    h[1] = __floats2half2_rn(v.z, v.w);
    *(uint2*)(Bfh + (size_t)n * ERD + j) = *(uint2*)h;
}

// ---------------------------------------------------------------------------
// Router: logits = x @ Wr^T (fp32), top-2 softmax;
// h'fp16 = fp16(sum_s hp[s] * wv[e] * SCALING)
// ---------------------------------------------------------------------------
__global__ __launch_bounds__(256)
void router_kernel(const float* __restrict__ x,
                   const float* __restrict__ Wr,
                   const float* __restrict__ hp,   // [KSPLIT][T][128]
                   __half* __restrict__ h,
                   int T)
{
    const int t = blockIdx.x;
    const float* xr = x + (size_t)t * D_INc;

    float acc[NEXP];
#pragma unroll
    for (int e = 0; e < NEXP; e++) acc[e] = 0.0f;
    for (int j = threadIdx.x; j < D_INc; j += 256) {
        float xv = xr[j];
#pragma unroll
        for (int e = 0; e < NEXP; e++) acc[e] += xv * Wr[e * D_INc + j];
    }
#pragma unroll
    for (int off = 16; off > 0; off >>= 1)
#pragma unroll
        for (int e = 0; e < NEXP; e++) acc[e] += __shfl_xor_sync(0xffffffffu, acc[e], off);

    __shared__ float sred[8][NEXP];
    const int warp = threadIdx.x >> 5;
    const int lane = threadIdx.x & 31;
    if (lane == 0)
#pragma unroll
        for (int e = 0; e < NEXP; e++) sred[warp][e] = acc[e];
    __syncthreads();

    __shared__ float wv[NEXP];
    if (threadIdx.x == 0) {
        float l[NEXP];
#pragma unroll
        for (int e = 0; e < NEXP; e++) {
            float s = 0.0f;
#pragma unroll
            for (int w = 0; w < 8; w++) s += sred[w][e];
            l[e] = s;
        }
        int i0 = 0;
#pragma unroll
        for (int e = 1; e < NEXP; e++) if (l[e] > l[i0]) i0 = e;
        int i1 = -1;
#pragma unroll
        for (int e = 0; e < NEXP; e++) {
            if (e == i0) continue;
            if (i1 < 0 || l[e] > l[i1]) i1 = e;
        }
        float m  = l[i0];
        float e0 = expf(l[i0] - m);
        float e1 = expf(l[i1] - m);
        float s  = e0 + e1;
#pragma unroll
        for (int e = 0; e < NEXP; e++) wv[e] = 0.0f;
        wv[i0] = e0 / s;
        wv[i1] = e1 / s;
    }
    __syncthreads();

    if (threadIdx.x < ERD) {
        int e = threadIdx.x >> 4;
        size_t base = (size_t)t * ERD + threadIdx.x;
        size_t ss = (size_t)T * ERD;
        float v = hp[base] + hp[base + ss] + hp[base + 2 * ss] + hp[base + 3 * ss];
        h[base] = __float2half_rn(v * (wv[e] * SCALINGF));
    }
}

// ---------------------------------------------------------------------------
extern "C" void kernel_launch(void* const* d_in, const int* in_sizes, int n_in,
                              void* d_out, int out_size)
{
    const float* x  = (const float*)d_in[0];   // [T, 4096]
    const float* Wb = (const float*)d_in[1];   // [4096, 4096]
    const float* bb = (const float*)d_in[2];   // [4096]
    const float* Wr = (const float*)d_in[3];   // [8, 4096]
    const float* Aw = (const float*)d_in[4];   // [8,16,4096] == [128,4096]
    const float* Bw = (const float*)d_in[5];   // [8,4096,16]
    float* out = (float*)d_out;

    const int T = in_sizes[0] / D_INc;         // 8192

    __half *xh, *wbh, *ah, *bfh, *hh;
    float  *hp;
    cudaGetSymbolAddress((void**)&xh,  g_xh);
    cudaGetSymbolAddress((void**)&wbh, g_Wbh);
    cudaGetSymbolAddress((void**)&ah,  g_Ah);
    cudaGetSymbolAddress((void**)&bfh, g_Bfh);
    cudaGetSymbolAddress((void**)&hh,  g_hh);
    cudaGetSymbolAddress((void**)&hp,  g_hp);

    constexpr int SMEM = 1024 + NSTG * STAGE_B;   // 111,616 B

    static bool attr_done = false;
    if (!attr_done) {
        cudaFuncSetAttribute(fused_gemm, cudaFuncAttributeMaxDynamicSharedMemorySize, SMEM);
        attr_done = true;
    }

    // --- prepass: fp16 conversions ---
    {
        int n8x = T * D_INc / 8;
        to_half_kernel<<<(n8x + 255) / 256, 256>>>(x, xh, n8x);
        int n8w = D_OUTc * D_INc / 8;
        to_half_kernel<<<(n8w + 255) / 256, 256>>>(Wb, wbh, n8w);
        int n8a = ERD * D_INc / 8;
        to_half_kernel<<<(n8a + 255) / 256, 256>>>(Aw, ah, n8a);
        repack_B_kernel<<<(D_OUTc * 32) / 256, 256>>>(Bw, bfh);
    }

    // --- h partials = x @ A^T, split-K across 4 slices (grid 4 x 64) ---
    fused_gemm<<<dim3(KSPLIT, T / 128), 256, SMEM>>>(
        xh, D_INc, ah, D_INc,
        xh, D_INc, ah, D_INc,
        D_INc / BKH / KSPLIT, 0, nullptr, hp, ERD,
        1, T * ERD);

    // --- router: top-2 softmax weights, reduce partials, scale h' -> fp16 ---
    router_kernel<<<T, 256>>>(x, Wr, hp, hh, T);

    // --- out = [x | h'] @ [Wb | Bf]^T + bias ---
    fused_gemm<<<dim3(D_OUTc / 128, T / 128), 256, SMEM>>>(
        xh, D_INc, wbh, D_INc,
        hh, ERD, bfh, ERD,
        D_INc / BKH, ERD / BKH, bb, out, D_OUTc,
        0, 0);
}